// round 4
// baseline (speedup 1.0000x reference)
#include <cuda_runtime.h>

// y = min(((x + 1) * 0.75)^2, 10)  — elementwise over 8192*8192 fp32.
// HBM-bound stream: 8 float4 per thread, ALL loads front-batched (MLP_p1=8),
// default cache ops (streaming hints regressed in R3), stores drain as one
// contiguous burst. 67108864 elems = 8192 blocks * 256 thr * 32 elems (exact).

#define T 256u

__device__ __forceinline__ float f(float x) {
    float t = (x + 1.0f) * 0.75f;
    float y = t * t;
    return fminf(y, 10.0f);
}

__device__ __forceinline__ float4 f4(float4 v) {
    float4 r;
    r.x = f(v.x); r.y = f(v.y); r.z = f(v.z); r.w = f(v.w);
    return r;
}

__global__ __launch_bounds__(256) void elemwise_kernel(const float4* __restrict__ in,
                                                       float4* __restrict__ out) {
    unsigned base = blockIdx.x * (T * 8u) + threadIdx.x;

    // Front-batch all 8 independent loads -> MLP=8.
    float4 v0 = in[base + 0u * T];
    float4 v1 = in[base + 1u * T];
    float4 v2 = in[base + 2u * T];
    float4 v3 = in[base + 3u * T];
    float4 v4 = in[base + 4u * T];
    float4 v5 = in[base + 5u * T];
    float4 v6 = in[base + 6u * T];
    float4 v7 = in[base + 7u * T];

    // Drain stores as one contiguous burst.
    out[base + 0u * T] = f4(v0);
    out[base + 1u * T] = f4(v1);
    out[base + 2u * T] = f4(v2);
    out[base + 3u * T] = f4(v3);
    out[base + 4u * T] = f4(v4);
    out[base + 5u * T] = f4(v5);
    out[base + 6u * T] = f4(v6);
    out[base + 7u * T] = f4(v7);
}

extern "C" void kernel_launch(void* const* d_in, const int* in_sizes, int n_in,
                              void* d_out, int out_size) {
    const float4* in = (const float4*)d_in[0];
    float4* out = (float4*)d_out;
    int n = in_sizes[0];            // 67108864
    int n4 = n / 4;                 // 16777216 float4s
    int blocks = n4 / (256 * 8);    // 8192, exact
    elemwise_kernel<<<blocks, 256>>>(in, out);
}

// round 5
// speedup vs baseline: 1.0074x; 1.0074x over previous
#include <cuda_runtime.h>

// y = min(((x + 1) * 0.75)^2, 10)  — elementwise over 8192*8192 fp32.
// HBM-bound stream, best-known structure (R2): 4 independent front-batched
// float4 loads per thread (MLP_p1=4), default cache ops, coalesced at
// blockDim stride. Block=512: 67108864 elems = 8192 blocks * 512 thr * 16.

#define T 512u

__device__ __forceinline__ float f(float x) {
    float t = (x + 1.0f) * 0.75f;
    float y = t * t;
    return fminf(y, 10.0f);
}

__device__ __forceinline__ float4 f4(float4 v) {
    float4 r;
    r.x = f(v.x); r.y = f(v.y); r.z = f(v.z); r.w = f(v.w);
    return r;
}

__global__ __launch_bounds__(512) void elemwise_kernel(const float4* __restrict__ in,
                                                       float4* __restrict__ out) {
    unsigned base = blockIdx.x * (T * 4u) + threadIdx.x;

    // Front-batch 4 independent loads -> MLP=4 (saturation point per R2/R4).
    float4 v0 = in[base + 0u * T];
    float4 v1 = in[base + 1u * T];
    float4 v2 = in[base + 2u * T];
    float4 v3 = in[base + 3u * T];

    out[base + 0u * T] = f4(v0);
    out[base + 1u * T] = f4(v1);
    out[base + 2u * T] = f4(v2);
    out[base + 3u * T] = f4(v3);
}

extern "C" void kernel_launch(void* const* d_in, const int* in_sizes, int n_in,
                              void* d_out, int out_size) {
    const float4* in = (const float4*)d_in[0];
    float4* out = (float4*)d_out;
    int n = in_sizes[0];            // 67108864
    int n4 = n / 4;                 // 16777216 float4s
    int blocks = n4 / (512 * 4);    // 8192, exact
    elemwise_kernel<<<blocks, 512>>>(in, out);
}